// round 1
// baseline (speedup 1.0000x reference)
#include <cuda_runtime.h>
#include <math.h>

#define NTOK 8192
#define DIM  1024

// Scratch (static device globals — no allocation in kernel_launch)
__device__ float g_Q[(size_t)NTOK * DIM];
__device__ float g_K[(size_t)NTOK * DIM];
__device__ float g_V[(size_t)NTOK * DIM];
__device__ float g_S[(size_t)NTOK * NTOK];

// ---------------------------------------------------------------------------
// QKV projection: out = x @ W^T + b   (NT GEMM, W row-major [D,D])
// grid: (NTOK/64, DIM/64, 3)   block: 256
// ---------------------------------------------------------------------------
__global__ __launch_bounds__(256) void qkv_kernel(
    const float* __restrict__ x,
    const float* __restrict__ Wq, const float* __restrict__ bq,
    const float* __restrict__ Wk, const float* __restrict__ bk,
    const float* __restrict__ Wv, const float* __restrict__ bv)
{
    __shared__ float As[16][64];
    __shared__ float Bs[16][64];

    const float* W; const float* b; float* out;
    switch (blockIdx.z) {
        case 0:  W = Wq; b = bq; out = g_Q; break;
        case 1:  W = Wk; b = bk; out = g_K; break;
        default: W = Wv; b = bv; out = g_V; break;
    }

    int tid = threadIdx.x;
    int tx = tid & 15, ty = tid >> 4;
    int rowBase = blockIdx.x * 64;
    int colBase = blockIdx.y * 64;

    int lr = tid >> 2;          // 0..63
    int lc = (tid & 3) * 4;     // 0,4,8,12

    const float* Ap = x + (size_t)(rowBase + lr) * DIM + lc;
    const float* Bp = W + (size_t)(colBase + lr) * DIM + lc;

    float acc[4][4] = {};

    for (int k0 = 0; k0 < DIM; k0 += 16) {
        float4 avec = *(const float4*)(Ap + k0);
        float4 bvec = *(const float4*)(Bp + k0);
        __syncthreads();
        As[lc+0][lr] = avec.x; As[lc+1][lr] = avec.y;
        As[lc+2][lr] = avec.z; As[lc+3][lr] = avec.w;
        Bs[lc+0][lr] = bvec.x; Bs[lc+1][lr] = bvec.y;
        Bs[lc+2][lr] = bvec.z; Bs[lc+3][lr] = bvec.w;
        __syncthreads();
        #pragma unroll
        for (int k = 0; k < 16; k++) {
            float a[4], bb[4];
            #pragma unroll
            for (int i = 0; i < 4; i++) a[i]  = As[k][ty*4 + i];
            #pragma unroll
            for (int j = 0; j < 4; j++) bb[j] = Bs[k][tx*4 + j];
            #pragma unroll
            for (int i = 0; i < 4; i++)
                #pragma unroll
                for (int j = 0; j < 4; j++)
                    acc[i][j] = fmaf(a[i], bb[j], acc[i][j]);
        }
    }

    #pragma unroll
    for (int i = 0; i < 4; i++) {
        int r = rowBase + ty*4 + i;
        #pragma unroll
        for (int j = 0; j < 4; j++) {
            int c = colBase + tx*4 + j;
            out[(size_t)r * DIM + c] = acc[i][j] + b[c];
        }
    }
}

// ---------------------------------------------------------------------------
// Scores: S = (Q @ K^T)/32 + log(exp(-|ti-tj|/86400) + 1e-10)
// grid: (NTOK/64, NTOK/64)   block: 256
// ---------------------------------------------------------------------------
__global__ __launch_bounds__(256) void scores_kernel(const float* __restrict__ ts)
{
    __shared__ float As[16][64];
    __shared__ float Bs[16][64];
    __shared__ float trow[64];
    __shared__ float tcol[64];

    int tid = threadIdx.x;
    int tx = tid & 15, ty = tid >> 4;
    int rowBase = blockIdx.x * 64;
    int colBase = blockIdx.y * 64;

    if (tid < 64)        trow[tid]      = ts[rowBase + tid];
    else if (tid < 128)  tcol[tid - 64] = ts[colBase + tid - 64];

    int lr = tid >> 2;
    int lc = (tid & 3) * 4;

    const float* Ap = g_Q + (size_t)(rowBase + lr) * DIM + lc;
    const float* Bp = g_K + (size_t)(colBase + lr) * DIM + lc;

    float acc[4][4] = {};

    for (int k0 = 0; k0 < DIM; k0 += 16) {
        float4 avec = *(const float4*)(Ap + k0);
        float4 bvec = *(const float4*)(Bp + k0);
        __syncthreads();
        As[lc+0][lr] = avec.x; As[lc+1][lr] = avec.y;
        As[lc+2][lr] = avec.z; As[lc+3][lr] = avec.w;
        Bs[lc+0][lr] = bvec.x; Bs[lc+1][lr] = bvec.y;
        Bs[lc+2][lr] = bvec.z; Bs[lc+3][lr] = bvec.w;
        __syncthreads();
        #pragma unroll
        for (int k = 0; k < 16; k++) {
            float a[4], bb[4];
            #pragma unroll
            for (int i = 0; i < 4; i++) a[i]  = As[k][ty*4 + i];
            #pragma unroll
            for (int j = 0; j < 4; j++) bb[j] = Bs[k][tx*4 + j];
            #pragma unroll
            for (int i = 0; i < 4; i++)
                #pragma unroll
                for (int j = 0; j < 4; j++)
                    acc[i][j] = fmaf(a[i], bb[j], acc[i][j]);
        }
    }

    const float inv_scale = 1.0f / 32.0f;        // 1/sqrt(1024)
    const float inv_T     = 1.0f / 86400.0f;

    #pragma unroll
    for (int i = 0; i < 4; i++) {
        int r = rowBase + ty*4 + i;
        float ti = trow[ty*4 + i];
        #pragma unroll
        for (int j = 0; j < 4; j++) {
            int c = colBase + tx*4 + j;
            float dt = fabsf(ti - tcol[tx*4 + j]);
            float bias = logf(expf(-dt * inv_T) + 1e-10f);
            g_S[(size_t)r * NTOK + c] = acc[i][j] * inv_scale + bias;
        }
    }
}

// ---------------------------------------------------------------------------
// Row softmax, in-place: S -> exp(S - m) / l
// grid: NTOK blocks of 256 threads, one row each
// ---------------------------------------------------------------------------
__global__ __launch_bounds__(256) void softmax_kernel()
{
    __shared__ float sm[256];
    __shared__ float sl[256];
    __shared__ float s_m, s_invl;

    int row = blockIdx.x;
    int tid = threadIdx.x;
    float* Srow = g_S + (size_t)row * NTOK;

    // Online (m, l)
    float m = -INFINITY, l = 0.0f;
    for (int j = tid; j < NTOK; j += 256) {
        float s = Srow[j];
        float nm = fmaxf(m, s);
        l = l * __expf(m - nm) + __expf(s - nm);
        m = nm;
    }
    sm[tid] = m; sl[tid] = l;
    __syncthreads();
    for (int off = 128; off > 0; off >>= 1) {
        if (tid < off) {
            float m2 = sm[tid + off], l2 = sl[tid + off];
            float m1 = sm[tid],       l1 = sl[tid];
            float nm = fmaxf(m1, m2);
            sl[tid] = l1 * __expf(m1 - nm) + l2 * __expf(m2 - nm);
            sm[tid] = nm;
        }
        __syncthreads();
    }
    if (tid == 0) { s_m = sm[0]; s_invl = 1.0f / sl[0]; }
    __syncthreads();

    float mm = s_m, invl = s_invl;
    for (int j = tid; j < NTOK; j += 256) {
        Srow[j] = __expf(Srow[j] - mm) * invl;
    }
}

// ---------------------------------------------------------------------------
// Output: O = P @ V   (NN GEMM, K = NTOK)
// grid: (NTOK/64, DIM/64)   block: 256
// ---------------------------------------------------------------------------
__global__ __launch_bounds__(256) void out_kernel(float* __restrict__ O)
{
    __shared__ float As[16][64];
    __shared__ float Bs[16][64];

    int tid = threadIdx.x;
    int tx = tid & 15, ty = tid >> 4;
    int rowBase = blockIdx.x * 64;
    int colBase = blockIdx.y * 64;

    // A tile loads (P, k-contiguous)
    int lr = tid >> 2;
    int lc = (tid & 3) * 4;
    const float* Ap = g_S + (size_t)(rowBase + lr) * NTOK + lc;

    // B tile loads (V, n-contiguous): 16 k-rows x 64 cols
    int br = tid >> 4;            // 0..15 (k)
    int bc = (tid & 15) * 4;      // 0..60
    const float* Bp = g_V + (size_t)br * DIM + colBase + bc;

    float acc[4][4] = {};

    for (int k0 = 0; k0 < NTOK; k0 += 16) {
        float4 avec = *(const float4*)(Ap + k0);
        float4 bvec = *(const float4*)(Bp + (size_t)k0 * DIM);
        __syncthreads();
        As[lc+0][lr] = avec.x; As[lc+1][lr] = avec.y;
        As[lc+2][lr] = avec.z; As[lc+3][lr] = avec.w;
        *(float4*)&Bs[br][bc] = bvec;
        __syncthreads();
        #pragma unroll
        for (int k = 0; k < 16; k++) {
            float a[4], bb[4];
            #pragma unroll
            for (int i = 0; i < 4; i++) a[i]  = As[k][ty*4 + i];
            #pragma unroll
            for (int j = 0; j < 4; j++) bb[j] = Bs[k][tx*4 + j];
            #pragma unroll
            for (int i = 0; i < 4; i++)
                #pragma unroll
                for (int j = 0; j < 4; j++)
                    acc[i][j] = fmaf(a[i], bb[j], acc[i][j]);
        }
    }

    #pragma unroll
    for (int i = 0; i < 4; i++) {
        int r = rowBase + ty*4 + i;
        #pragma unroll
        for (int j = 0; j < 4; j++) {
            int c = colBase + tx*4 + j;
            O[(size_t)r * DIM + c] = acc[i][j];
        }
    }
}

// ---------------------------------------------------------------------------
extern "C" void kernel_launch(void* const* d_in, const int* in_sizes, int n_in,
                              void* d_out, int out_size)
{
    const float* x  = (const float*)d_in[0];
    const float* ts = (const float*)d_in[1];
    const float* Wq = (const float*)d_in[2];
    const float* bq = (const float*)d_in[3];
    const float* Wk = (const float*)d_in[4];
    const float* bk = (const float*)d_in[5];
    const float* Wv = (const float*)d_in[6];
    const float* bv = (const float*)d_in[7];
    float* out = (float*)d_out;

    qkv_kernel<<<dim3(NTOK/64, DIM/64, 3), 256>>>(x, Wq, bq, Wk, bk, Wv, bv);
    scores_kernel<<<dim3(NTOK/64, NTOK/64), 256>>>(ts);
    softmax_kernel<<<NTOK, 256>>>();
    out_kernel<<<dim3(NTOK/64, DIM/64), 256>>>(out);
}

// round 2
// speedup vs baseline: 2.6814x; 2.6814x over previous
#include <cuda_runtime.h>
#include <cuda_bf16.h>
#include <math.h>

#define NTOK 8192
#define DIM  1024
#define KT   32          // k-tile depth (bf16 elements)
#define BPAD 40          // smem row stride in bf16 (32 + 8 pad, 80B = 5*16B aligned)

// Scratch (static device globals — no allocation in kernel_launch)
__device__ float g_Q[(size_t)NTOK * DIM];
__device__ float g_K[(size_t)NTOK * DIM];
__device__ float g_V[(size_t)NTOK * DIM];
__device__ float g_S[(size_t)NTOK * NTOK];

// ---------------------------------------------------------------------------
// helpers
// ---------------------------------------------------------------------------
__device__ __forceinline__ unsigned smem_u32(const void* p) {
    return (unsigned)__cvta_generic_to_shared(p);
}

__device__ __forceinline__ void ldsm4(unsigned r[4], unsigned addr) {
    asm volatile("ldmatrix.sync.aligned.m8n8.x4.shared.b16 {%0,%1,%2,%3},[%4];"
                 : "=r"(r[0]), "=r"(r[1]), "=r"(r[2]), "=r"(r[3]) : "r"(addr));
}

__device__ __forceinline__ void mma_bf16(float c[4], const unsigned a[4], const unsigned b[2]) {
    asm volatile("mma.sync.aligned.m16n8k16.row.col.f32.bf16.bf16.f32 "
                 "{%0,%1,%2,%3},{%4,%5,%6,%7},{%8,%9},{%0,%1,%2,%3};"
                 : "+f"(c[0]), "+f"(c[1]), "+f"(c[2]), "+f"(c[3])
                 : "r"(a[0]), "r"(a[1]), "r"(a[2]), "r"(a[3]), "r"(b[0]), "r"(b[1]));
}

// fp32 -> (hi, lo) bf16 split, 4 elements, stored as bf16x2 pairs
__device__ __forceinline__ void cvt_store4(__nv_bfloat16* dh, __nv_bfloat16* dl, float4 v) {
    float f[4] = {v.x, v.y, v.z, v.w};
    __nv_bfloat16 h[4], l[4];
#pragma unroll
    for (int i = 0; i < 4; i++) {
        h[i] = __float2bfloat16(f[i]);
        l[i] = __float2bfloat16(f[i] - __bfloat162float(h[i]));
    }
    ((__nv_bfloat162*)dh)[0] = __halves2bfloat162(h[0], h[1]);
    ((__nv_bfloat162*)dh)[1] = __halves2bfloat162(h[2], h[3]);
    ((__nv_bfloat162*)dl)[0] = __halves2bfloat162(l[0], l[1]);
    ((__nv_bfloat162*)dl)[1] = __halves2bfloat162(l[2], l[3]);
}

// Compute one 128x128 x KT tile: acc += split-MMA(A, B)
// A smem: [128 rows m][k], B smem: [128 rows n][k]
__device__ __forceinline__ void mma_tile(
    const __nv_bfloat16 (*Ah)[BPAD], const __nv_bfloat16 (*Al)[BPAD],
    const __nv_bfloat16 (*Bh)[BPAD], const __nv_bfloat16 (*Bl)[BPAD],
    int lane, int wm, int wn, float acc[4][4][4])
{
#pragma unroll
    for (int kk = 0; kk < KT; kk += 16) {
        unsigned ah[4][4], al[4][4], bh[2][4], bl[2][4];
        int arow = (lane & 7) + ((lane >> 3) & 1) * 8;
        int acol = kk + (lane >> 4) * 8;
#pragma unroll
        for (int mi = 0; mi < 4; mi++) {
            int r = wm * 64 + mi * 16 + arow;
            ldsm4(ah[mi], smem_u32(&Ah[r][acol]));
            ldsm4(al[mi], smem_u32(&Al[r][acol]));
        }
        int brow = (lane & 7) + ((lane >> 4) & 1) * 8;
        int bcol = kk + ((lane >> 3) & 1) * 8;
#pragma unroll
        for (int p = 0; p < 2; p++) {
            int n = wn * 32 + p * 16 + brow;
            ldsm4(bh[p], smem_u32(&Bh[n][bcol]));
            ldsm4(bl[p], smem_u32(&Bl[n][bcol]));
        }
#pragma unroll
        for (int mi = 0; mi < 4; mi++)
#pragma unroll
            for (int ni = 0; ni < 4; ni++) {
                const unsigned* bhp = &bh[ni >> 1][(ni & 1) * 2];
                const unsigned* blp = &bl[ni >> 1][(ni & 1) * 2];
                mma_bf16(acc[mi][ni], ah[mi], bhp);
                mma_bf16(acc[mi][ni], ah[mi], blp);
                mma_bf16(acc[mi][ni], al[mi], bhp);
            }
    }
}

// ---------------------------------------------------------------------------
// QKV projection: out = x @ W^T + b.  A=x [m][k], B=W [n][k] (both k-contig)
// grid (64, 8, 3), block 256
// ---------------------------------------------------------------------------
__global__ __launch_bounds__(256, 1) void qkv_mma(
    const float* __restrict__ x,
    const float* __restrict__ Wq, const float* __restrict__ bq,
    const float* __restrict__ Wk, const float* __restrict__ bk,
    const float* __restrict__ Wv, const float* __restrict__ bv)
{
    __shared__ __align__(16) __nv_bfloat16 Ah[128][BPAD], Al[128][BPAD];
    __shared__ __align__(16) __nv_bfloat16 Bh[128][BPAD], Bl[128][BPAD];

    const float* W; const float* bias; float* out;
    switch (blockIdx.z) {
        case 0:  W = Wq; bias = bq; out = g_Q; break;
        case 1:  W = Wk; bias = bk; out = g_K; break;
        default: W = Wv; bias = bv; out = g_V; break;
    }

    int tid = threadIdx.x, lane = tid & 31, warp = tid >> 5;
    int wm = warp >> 2, wn = warp & 3;
    int rowBase = blockIdx.x * 128, colBase = blockIdx.y * 128;

    const float* Ag = x + (size_t)rowBase * DIM;
    const float* Bg = W + (size_t)colBase * DIM;

    int r0 = tid >> 3, kc = (tid & 7) * 4;
    float acc[4][4][4] = {};

    float4 abuf[4], bbuf[4];
#pragma unroll
    for (int it = 0; it < 4; it++) {
        int r = r0 + it * 32;
        abuf[it] = *(const float4*)(Ag + (size_t)r * DIM + kc);
        bbuf[it] = *(const float4*)(Bg + (size_t)r * DIM + kc);
    }

    for (int k0 = 0; k0 < DIM; k0 += KT) {
        __syncthreads();
#pragma unroll
        for (int it = 0; it < 4; it++) {
            int r = r0 + it * 32;
            cvt_store4(&Ah[r][kc], &Al[r][kc], abuf[it]);
            cvt_store4(&Bh[r][kc], &Bl[r][kc], bbuf[it]);
        }
        __syncthreads();
        if (k0 + KT < DIM) {
#pragma unroll
            for (int it = 0; it < 4; it++) {
                int r = r0 + it * 32;
                abuf[it] = *(const float4*)(Ag + (size_t)r * DIM + k0 + KT + kc);
                bbuf[it] = *(const float4*)(Bg + (size_t)r * DIM + k0 + KT + kc);
            }
        }
        mma_tile(Ah, Al, Bh, Bl, lane, wm, wn, acc);
    }

#pragma unroll
    for (int mi = 0; mi < 4; mi++)
#pragma unroll
        for (int ni = 0; ni < 4; ni++) {
            int r = rowBase + wm * 64 + mi * 16 + (lane >> 2);
            int c = colBase + wn * 32 + ni * 8 + (lane & 3) * 2;
            float b0 = bias[c], b1 = bias[c + 1];
            *(float2*)(out + (size_t)r * DIM + c) =
                make_float2(acc[mi][ni][0] + b0, acc[mi][ni][1] + b1);
            *(float2*)(out + (size_t)(r + 8) * DIM + c) =
                make_float2(acc[mi][ni][2] + b0, acc[mi][ni][3] + b1);
        }
}

// ---------------------------------------------------------------------------
// Scores: S = (Q @ K^T)/32 + log(exp(-|ti-tj|/86400)+1e-10)
// grid (64, 64), block 256
// ---------------------------------------------------------------------------
__global__ __launch_bounds__(256, 1) void scores_mma(const float* __restrict__ ts)
{
    __shared__ __align__(16) __nv_bfloat16 Ah[128][BPAD], Al[128][BPAD];
    __shared__ __align__(16) __nv_bfloat16 Bh[128][BPAD], Bl[128][BPAD];

    int tid = threadIdx.x, lane = tid & 31, warp = tid >> 5;
    int wm = warp >> 2, wn = warp & 3;
    int rowBase = blockIdx.x * 128, colBase = blockIdx.y * 128;

    const float* Ag = g_Q + (size_t)rowBase * DIM;
    const float* Bg = g_K + (size_t)colBase * DIM;

    int r0 = tid >> 3, kc = (tid & 7) * 4;
    float acc[4][4][4] = {};

    float4 abuf[4], bbuf[4];
#pragma unroll
    for (int it = 0; it < 4; it++) {
        int r = r0 + it * 32;
        abuf[it] = *(const float4*)(Ag + (size_t)r * DIM + kc);
        bbuf[it] = *(const float4*)(Bg + (size_t)r * DIM + kc);
    }

    for (int k0 = 0; k0 < DIM; k0 += KT) {
        __syncthreads();
#pragma unroll
        for (int it = 0; it < 4; it++) {
            int r = r0 + it * 32;
            cvt_store4(&Ah[r][kc], &Al[r][kc], abuf[it]);
            cvt_store4(&Bh[r][kc], &Bl[r][kc], bbuf[it]);
        }
        __syncthreads();
        if (k0 + KT < DIM) {
#pragma unroll
            for (int it = 0; it < 4; it++) {
                int r = r0 + it * 32;
                abuf[it] = *(const float4*)(Ag + (size_t)r * DIM + k0 + KT + kc);
                bbuf[it] = *(const float4*)(Bg + (size_t)r * DIM + k0 + KT + kc);
            }
        }
        mma_tile(Ah, Al, Bh, Bl, lane, wm, wn, acc);
    }

    const float inv_scale = 1.0f / 32.0f;
    const float inv_T = 1.0f / 86400.0f;

#pragma unroll
    for (int mi = 0; mi < 4; mi++) {
        int r = rowBase + wm * 64 + mi * 16 + (lane >> 2);
        float t_r0 = ts[r], t_r1 = ts[r + 8];
#pragma unroll
        for (int ni = 0; ni < 4; ni++) {
            int c = colBase + wn * 32 + ni * 8 + (lane & 3) * 2;
            float tc0 = ts[c], tc1 = ts[c + 1];
            float b00 = logf(expf(-fabsf(t_r0 - tc0) * inv_T) + 1e-10f);
            float b01 = logf(expf(-fabsf(t_r0 - tc1) * inv_T) + 1e-10f);
            float b10 = logf(expf(-fabsf(t_r1 - tc0) * inv_T) + 1e-10f);
            float b11 = logf(expf(-fabsf(t_r1 - tc1) * inv_T) + 1e-10f);
            *(float2*)(g_S + (size_t)r * NTOK + c) =
                make_float2(acc[mi][ni][0] * inv_scale + b00, acc[mi][ni][1] * inv_scale + b01);
            *(float2*)(g_S + (size_t)(r + 8) * NTOK + c) =
                make_float2(acc[mi][ni][2] * inv_scale + b10, acc[mi][ni][3] * inv_scale + b11);
        }
    }
}

// ---------------------------------------------------------------------------
// Row softmax, in-place
// ---------------------------------------------------------------------------
__global__ __launch_bounds__(256) void softmax_kernel()
{
    __shared__ float sm[256];
    __shared__ float sl[256];
    __shared__ float s_m, s_invl;

    int row = blockIdx.x;
    int tid = threadIdx.x;
    float* Srow = g_S + (size_t)row * NTOK;

    float m = -INFINITY, l = 0.0f;
    for (int j = tid; j < NTOK; j += 256) {
        float s = Srow[j];
        float nm = fmaxf(m, s);
        l = l * __expf(m - nm) + __expf(s - nm);
        m = nm;
    }
    sm[tid] = m; sl[tid] = l;
    __syncthreads();
    for (int off = 128; off > 0; off >>= 1) {
        if (tid < off) {
            float m2 = sm[tid + off], l2 = sl[tid + off];
            float m1 = sm[tid], l1 = sl[tid];
            float nm = fmaxf(m1, m2);
            sl[tid] = l1 * __expf(m1 - nm) + l2 * __expf(m2 - nm);
            sm[tid] = nm;
        }
        __syncthreads();
    }
    if (tid == 0) { s_m = sm[0]; s_invl = 1.0f / sl[0]; }
    __syncthreads();

    float mm = s_m, invl = s_invl;
    for (int j = tid; j < NTOK; j += 256) {
        Srow[j] = __expf(Srow[j] - mm) * invl;
    }
}

// ---------------------------------------------------------------------------
// Output: O = P @ V.  A = P [m][k] (k-contig), B = V [k][n] -> transposed stage
// grid (64, 8), block 256
// ---------------------------------------------------------------------------
__global__ __launch_bounds__(256, 1) void out_mma(float* __restrict__ O)
{
    __shared__ __align__(16) __nv_bfloat16 Ah[128][BPAD], Al[128][BPAD];
    __shared__ __align__(16) __nv_bfloat16 Bh[128][BPAD], Bl[128][BPAD];

    int tid = threadIdx.x, lane = tid & 31, warp = tid >> 5;
    int wm = warp >> 2, wn = warp & 3;
    int rowBase = blockIdx.x * 128, colBase = blockIdx.y * 128;

    const float* Ag = g_S + (size_t)rowBase * NTOK;

    int r0 = tid >> 3, kc = (tid & 7) * 4;   // A staging
    int vk = tid >> 3, vn0 = (tid & 7);      // V staging: k row, n chunk base
    float acc[4][4][4] = {};

    float4 abuf[4], bbuf[4];
#pragma unroll
    for (int it = 0; it < 4; it++) {
        abuf[it] = *(const float4*)(Ag + (size_t)(r0 + it * 32) * NTOK + kc);
        int n = (vn0 + it * 8) * 4;
        bbuf[it] = *(const float4*)(g_V + (size_t)vk * DIM + colBase + n);
    }

    for (int k0 = 0; k0 < NTOK; k0 += KT) {
        __syncthreads();
#pragma unroll
        for (int it = 0; it < 4; it++) {
            int r = r0 + it * 32;
            cvt_store4(&Ah[r][kc], &Al[r][kc], abuf[it]);
            // transpose V: bbuf[it] holds V[k0+vk][colBase + n .. n+3]
            int n = (vn0 + it * 8) * 4;
            float f[4] = {bbuf[it].x, bbuf[it].y, bbuf[it].z, bbuf[it].w};
#pragma unroll
            for (int j = 0; j < 4; j++) {
                __nv_bfloat16 h = __float2bfloat16(f[j]);
                Bh[n + j][vk] = h;
                Bl[n + j][vk] = __float2bfloat16(f[j] - __bfloat162float(h));
            }
        }
        __syncthreads();
        if (k0 + KT < NTOK) {
#pragma unroll
            for (int it = 0; it < 4; it++) {
                abuf[it] = *(const float4*)(Ag + (size_t)(r0 + it * 32) * NTOK + k0 + KT + kc);
                int n = (vn0 + it * 8) * 4;
                bbuf[it] = *(const float4*)(g_V + (size_t)(k0 + KT + vk) * DIM + colBase + n);
            }
        }
        mma_tile(Ah, Al, Bh, Bl, lane, wm, wn, acc);
    }

#pragma unroll
    for (int mi = 0; mi < 4; mi++)
#pragma unroll
        for (int ni = 0; ni < 4; ni++) {
            int r = rowBase + wm * 64 + mi * 16 + (lane >> 2);
            int c = colBase + wn * 32 + ni * 8 + (lane & 3) * 2;
            *(float2*)(O + (size_t)r * DIM + c) = make_float2(acc[mi][ni][0], acc[mi][ni][1]);
            *(float2*)(O + (size_t)(r + 8) * DIM + c) = make_float2(acc[mi][ni][2], acc[mi][ni][3]);
        }
}

// ---------------------------------------------------------------------------
extern "C" void kernel_launch(void* const* d_in, const int* in_sizes, int n_in,
                              void* d_out, int out_size)
{
    const float* x  = (const float*)d_in[0];
    const float* ts = (const float*)d_in[1];
    const float* Wq = (const float*)d_in[2];
    const float* bq = (const float*)d_in[3];
    const float* Wk = (const float*)d_in[4];
    const float* bk = (const float*)d_in[5];
    const float* Wv = (const float*)d_in[6];
    const float* bv = (const float*)d_in[7];
    float* out = (float*)d_out;

    qkv_mma<<<dim3(NTOK / 128, DIM / 128, 3), 256>>>(x, Wq, bq, Wk, bk, Wv, bv);
    scores_mma<<<dim3(NTOK / 128, NTOK / 128), 256>>>(ts);
    softmax_kernel<<<NTOK, 256>>>();
    out_mma<<<dim3(NTOK / 128, DIM / 128), 256>>>(out);
}

// round 3
// speedup vs baseline: 2.9924x; 1.1160x over previous
#include <cuda_runtime.h>
#include <cuda_bf16.h>
#include <math.h>

#define NTOK 8192
#define DIM  1024
#define KT   32          // k-tile depth (bf16 elements)
#define BPADE 40         // smem row stride in elements (80B = 5*16B)
#define ARR_BYTES 10240  // 128 * 40 * 2
#define STAGE_BYTES 40960
#define SMEM_TOTAL 81920

// ---------------------------------------------------------------------------
// Scratch (static device globals)
// ---------------------------------------------------------------------------
__device__ __nv_bfloat16 g_xh[(size_t)NTOK * DIM], g_xl[(size_t)NTOK * DIM];
__device__ __nv_bfloat16 g_Wh[3][(size_t)DIM * DIM], g_Wl[3][(size_t)DIM * DIM];
__device__ __nv_bfloat16 g_Qh[(size_t)NTOK * DIM], g_Ql[(size_t)NTOK * DIM];
__device__ __nv_bfloat16 g_Kh[(size_t)NTOK * DIM], g_Kl[(size_t)NTOK * DIM];
__device__ __nv_bfloat16 g_Vth[(size_t)DIM * NTOK], g_Vtl[(size_t)DIM * NTOK];  // [dim][token]
__device__ __nv_bfloat16 g_Ph[(size_t)NTOK * NTOK], g_Pl[(size_t)NTOK * NTOK];
__device__ float g_S[(size_t)NTOK * NTOK];

// ---------------------------------------------------------------------------
// helpers
// ---------------------------------------------------------------------------
__device__ __forceinline__ unsigned smem_u32(const void* p) {
    return (unsigned)__cvta_generic_to_shared(p);
}
__device__ __forceinline__ void cpa16(unsigned s, const void* g) {
    asm volatile("cp.async.cg.shared.global [%0],[%1],16;" :: "r"(s), "l"(g));
}
__device__ __forceinline__ void cpa_commit() {
    asm volatile("cp.async.commit_group;" ::: "memory");
}
__device__ __forceinline__ void cpa_wait0() {
    asm volatile("cp.async.wait_group 0;" ::: "memory");
}
__device__ __forceinline__ void ldsm4(unsigned r[4], unsigned addr) {
    asm volatile("ldmatrix.sync.aligned.m8n8.x4.shared.b16 {%0,%1,%2,%3},[%4];"
                 : "=r"(r[0]), "=r"(r[1]), "=r"(r[2]), "=r"(r[3]) : "r"(addr));
}
__device__ __forceinline__ void mma_bf16(float c[4], const unsigned a[4], const unsigned b[2]) {
    asm volatile("mma.sync.aligned.m16n8k16.row.col.f32.bf16.bf16.f32 "
                 "{%0,%1,%2,%3},{%4,%5,%6,%7},{%8,%9},{%0,%1,%2,%3};"
                 : "+f"(c[0]), "+f"(c[1]), "+f"(c[2]), "+f"(c[3])
                 : "r"(a[0]), "r"(a[1]), "r"(a[2]), "r"(a[3]), "r"(b[0]), "r"(b[1]));
}

// one 128x128xKT tile of split-MMA from staged smem
__device__ __forceinline__ void mma_tile(const char* sb, int lane, int wm, int wn,
                                         float acc[4][4][4])
{
    const __nv_bfloat16 (*Ah)[BPADE] = (const __nv_bfloat16(*)[BPADE])(sb);
    const __nv_bfloat16 (*Al)[BPADE] = (const __nv_bfloat16(*)[BPADE])(sb + ARR_BYTES);
    const __nv_bfloat16 (*Bh)[BPADE] = (const __nv_bfloat16(*)[BPADE])(sb + 2 * ARR_BYTES);
    const __nv_bfloat16 (*Bl)[BPADE] = (const __nv_bfloat16(*)[BPADE])(sb + 3 * ARR_BYTES);

#pragma unroll
    for (int kk = 0; kk < KT; kk += 16) {
        unsigned ah[4][4], al[4][4], bh[2][4], bl[2][4];
        int arow = (lane & 7) + ((lane >> 3) & 1) * 8;
        int acol = kk + (lane >> 4) * 8;
#pragma unroll
        for (int mi = 0; mi < 4; mi++) {
            int r = wm * 64 + mi * 16 + arow;
            ldsm4(ah[mi], smem_u32(&Ah[r][acol]));
            ldsm4(al[mi], smem_u32(&Al[r][acol]));
        }
        int brow = (lane & 7) + ((lane >> 4) & 1) * 8;
        int bcol = kk + ((lane >> 3) & 1) * 8;
#pragma unroll
        for (int p = 0; p < 2; p++) {
            int n = wn * 32 + p * 16 + brow;
            ldsm4(bh[p], smem_u32(&Bh[n][bcol]));
            ldsm4(bl[p], smem_u32(&Bl[n][bcol]));
        }
#pragma unroll
        for (int mi = 0; mi < 4; mi++)
#pragma unroll
            for (int ni = 0; ni < 4; ni++) {
                const unsigned* bhp = &bh[ni >> 1][(ni & 1) * 2];
                const unsigned* blp = &bl[ni >> 1][(ni & 1) * 2];
                mma_bf16(acc[mi][ni], ah[mi], bhp);
                mma_bf16(acc[mi][ni], ah[mi], blp);
                mma_bf16(acc[mi][ni], al[mi], bhp);
            }
    }
}

// Double-buffered mainloop. A rows at rowBase, B rows at colBase, both k-contig.
template <int KITERS>
__device__ __forceinline__ void gemm_core(
    const __nv_bfloat16* __restrict__ Agh, const __nv_bfloat16* __restrict__ Agl, int sA,
    const __nv_bfloat16* __restrict__ Bgh, const __nv_bfloat16* __restrict__ Bgl, int sB,
    int rowBase, int colBase, char* smem, float acc[4][4][4])
{
    int tid = threadIdx.x;
    int row = tid >> 2, ck = (tid & 3) * 8;

    const __nv_bfloat16* gAh0 = Agh + (size_t)(rowBase + row) * sA + ck;
    const __nv_bfloat16* gAh1 = gAh0 + (size_t)64 * sA;
    const __nv_bfloat16* gAl0 = Agl + (size_t)(rowBase + row) * sA + ck;
    const __nv_bfloat16* gAl1 = gAl0 + (size_t)64 * sA;
    const __nv_bfloat16* gBh0 = Bgh + (size_t)(colBase + row) * sB + ck;
    const __nv_bfloat16* gBh1 = gBh0 + (size_t)64 * sB;
    const __nv_bfloat16* gBl0 = Bgl + (size_t)(colBase + row) * sB + ck;
    const __nv_bfloat16* gBl1 = gBl0 + (size_t)64 * sB;

    unsigned s0 = smem_u32(smem) + (row * BPADE + ck) * 2;
    const unsigned R64 = 64 * BPADE * 2;

    int lane = tid & 31, warp = tid >> 5, wm = warp >> 2, wn = warp & 3;

    // prologue: stage 0
    {
        unsigned b = s0;
        cpa16(b, gAh0);                      cpa16(b + R64, gAh1);
        cpa16(b + ARR_BYTES, gAl0);          cpa16(b + ARR_BYTES + R64, gAl1);
        cpa16(b + 2 * ARR_BYTES, gBh0);      cpa16(b + 2 * ARR_BYTES + R64, gBh1);
        cpa16(b + 3 * ARR_BYTES, gBl0);      cpa16(b + 3 * ARR_BYTES + R64, gBl1);
        cpa_commit();
        gAh0 += KT; gAh1 += KT; gAl0 += KT; gAl1 += KT;
        gBh0 += KT; gBh1 += KT; gBl0 += KT; gBl1 += KT;
    }

    for (int it = 0; it < KITERS; it++) {
        cpa_wait0();
        __syncthreads();
        if (it + 1 < KITERS) {
            unsigned b = s0 + ((it + 1) & 1) * STAGE_BYTES;
            cpa16(b, gAh0);                      cpa16(b + R64, gAh1);
            cpa16(b + ARR_BYTES, gAl0);          cpa16(b + ARR_BYTES + R64, gAl1);
            cpa16(b + 2 * ARR_BYTES, gBh0);      cpa16(b + 2 * ARR_BYTES + R64, gBh1);
            cpa16(b + 3 * ARR_BYTES, gBl0);      cpa16(b + 3 * ARR_BYTES + R64, gBl1);
            cpa_commit();
            gAh0 += KT; gAh1 += KT; gAl0 += KT; gAl1 += KT;
            gBh0 += KT; gBh1 += KT; gBl0 += KT; gBl1 += KT;
        }
        mma_tile(smem + (it & 1) * STAGE_BYTES, lane, wm, wn, acc);
    }
}

// ---------------------------------------------------------------------------
// elementwise fp32 -> bf16 hi/lo split
// ---------------------------------------------------------------------------
__global__ __launch_bounds__(256) void split_kernel(
    const float* __restrict__ src, __nv_bfloat16* __restrict__ h,
    __nv_bfloat16* __restrict__ l, int n)
{
    int i = (blockIdx.x * 256 + threadIdx.x) * 4;
    if (i >= n) return;
    float4 v = *(const float4*)(src + i);
    float f[4] = {v.x, v.y, v.z, v.w};
    __nv_bfloat16 hh[4], ll[4];
#pragma unroll
    for (int j = 0; j < 4; j++) {
        hh[j] = __float2bfloat16(f[j]);
        ll[j] = __float2bfloat16(f[j] - __bfloat162float(hh[j]));
    }
    ((__nv_bfloat162*)(h + i))[0] = __halves2bfloat162(hh[0], hh[1]);
    ((__nv_bfloat162*)(h + i))[1] = __halves2bfloat162(hh[2], hh[3]);
    ((__nv_bfloat162*)(l + i))[0] = __halves2bfloat162(ll[0], ll[1]);
    ((__nv_bfloat162*)(l + i))[1] = __halves2bfloat162(ll[2], ll[3]);
}

// ---------------------------------------------------------------------------
// QKV: out = x @ W^T + b, split-stored. z=2 (V) stored transposed [dim][token].
// grid (64, 8, 3), block 256
// ---------------------------------------------------------------------------
__global__ __launch_bounds__(256, 1) void qkv_mma(
    const float* __restrict__ bq, const float* __restrict__ bk,
    const float* __restrict__ bv)
{
    extern __shared__ char smem[];
    int z = blockIdx.z;
    const float* bias = (z == 0) ? bq : (z == 1) ? bk : bv;

    int tid = threadIdx.x, lane = tid & 31, warp = tid >> 5;
    int wm = warp >> 2, wn = warp & 3;
    int rowBase = blockIdx.x * 128, colBase = blockIdx.y * 128;

    float acc[4][4][4] = {};
    gemm_core<DIM / KT>(g_xh, g_xl, DIM, g_Wh[z], g_Wl[z], DIM,
                        rowBase, colBase, smem, acc);

    if (z < 2) {
        __nv_bfloat16* oh = (z == 0) ? g_Qh : g_Kh;
        __nv_bfloat16* ol = (z == 0) ? g_Ql : g_Kl;
#pragma unroll
        for (int mi = 0; mi < 4; mi++)
#pragma unroll
            for (int ni = 0; ni < 4; ni++) {
                int r = rowBase + wm * 64 + mi * 16 + (lane >> 2);
                int c = colBase + wn * 32 + ni * 8 + (lane & 3) * 2;
                float b0 = bias[c], b1 = bias[c + 1];
#pragma unroll
                for (int hr = 0; hr < 2; hr++) {
                    float v0 = acc[mi][ni][hr * 2] + b0;
                    float v1 = acc[mi][ni][hr * 2 + 1] + b1;
                    __nv_bfloat16 h0 = __float2bfloat16(v0), h1 = __float2bfloat16(v1);
                    size_t o = (size_t)(r + hr * 8) * DIM + c;
                    *(__nv_bfloat162*)(oh + o) = __halves2bfloat162(h0, h1);
                    *(__nv_bfloat162*)(ol + o) = __halves2bfloat162(
                        __float2bfloat16(v0 - __bfloat162float(h0)),
                        __float2bfloat16(v1 - __bfloat162float(h1)));
                }
            }
    } else {
        // V: transpose via smem, store [dim][token]
        __syncthreads();  // done with mainloop buffers
        __nv_bfloat16 (*Th)[136] = (__nv_bfloat16(*)[136])(smem);
        __nv_bfloat16 (*Tl)[136] = (__nv_bfloat16(*)[136])(smem + 128 * 136 * 2);
#pragma unroll
        for (int mi = 0; mi < 4; mi++)
#pragma unroll
            for (int ni = 0; ni < 4; ni++) {
                int rL = wm * 64 + mi * 16 + (lane >> 2);
                int cL = wn * 32 + ni * 8 + (lane & 3) * 2;
                float b0 = bias[colBase + cL], b1 = bias[colBase + cL + 1];
#pragma unroll
                for (int hr = 0; hr < 2; hr++) {
                    float v0 = acc[mi][ni][hr * 2] + b0;
                    float v1 = acc[mi][ni][hr * 2 + 1] + b1;
                    __nv_bfloat16 h0 = __float2bfloat16(v0), h1 = __float2bfloat16(v1);
                    Th[cL][rL + hr * 8] = h0;
                    Th[cL + 1][rL + hr * 8] = h1;
                    Tl[cL][rL + hr * 8] = __float2bfloat16(v0 - __bfloat162float(h0));
                    Tl[cL + 1][rL + hr * 8] = __float2bfloat16(v1 - __bfloat162float(h1));
                }
            }
        __syncthreads();
#pragma unroll
        for (int j = 0; j < 8; j++) {
            int idx = j * 256 + tid;
            int cRow = idx >> 4, ch = (idx & 15) * 8;
            float4 vh = *(float4*)&Th[cRow][ch];
            float4 vl = *(float4*)&Tl[cRow][ch];
            size_t o = (size_t)(colBase + cRow) * NTOK + rowBase + ch;
            *(float4*)(g_Vth + o) = vh;
            *(float4*)(g_Vtl + o) = vl;
        }
    }
}

// ---------------------------------------------------------------------------
// Scores: S = (Q @ K^T)/32 + log(exp(-|dt|/86400)+1e-10).  grid (64,64)
// ---------------------------------------------------------------------------
__global__ __launch_bounds__(256, 1) void scores_mma(const float* __restrict__ ts)
{
    extern __shared__ char smem[];
    int tid = threadIdx.x, lane = tid & 31, warp = tid >> 5;
    int wm = warp >> 2, wn = warp & 3;
    int rowBase = blockIdx.x * 128, colBase = blockIdx.y * 128;

    float acc[4][4][4] = {};
    gemm_core<DIM / KT>(g_Qh, g_Ql, DIM, g_Kh, g_Kl, DIM,
                        rowBase, colBase, smem, acc);

    const float inv_scale = 1.0f / 32.0f;
    const float inv_T = 1.0f / 86400.0f;

#pragma unroll
    for (int mi = 0; mi < 4; mi++) {
        int r = rowBase + wm * 64 + mi * 16 + (lane >> 2);
        float t_r0 = ts[r], t_r1 = ts[r + 8];
#pragma unroll
        for (int ni = 0; ni < 4; ni++) {
            int c = colBase + wn * 32 + ni * 8 + (lane & 3) * 2;
            float tc0 = ts[c], tc1 = ts[c + 1];
            float b00 = logf(expf(-fabsf(t_r0 - tc0) * inv_T) + 1e-10f);
            float b01 = logf(expf(-fabsf(t_r0 - tc1) * inv_T) + 1e-10f);
            float b10 = logf(expf(-fabsf(t_r1 - tc0) * inv_T) + 1e-10f);
            float b11 = logf(expf(-fabsf(t_r1 - tc1) * inv_T) + 1e-10f);
            *(float2*)(g_S + (size_t)r * NTOK + c) =
                make_float2(acc[mi][ni][0] * inv_scale + b00, acc[mi][ni][1] * inv_scale + b01);
            *(float2*)(g_S + (size_t)(r + 8) * NTOK + c) =
                make_float2(acc[mi][ni][2] * inv_scale + b10, acc[mi][ni][3] * inv_scale + b11);
        }
    }
}

// ---------------------------------------------------------------------------
// Row softmax: S -> P (bf16 hi/lo).  grid NTOK, block 256
// ---------------------------------------------------------------------------
__global__ __launch_bounds__(256) void softmax_kernel()
{
    __shared__ float sm[256];
    __shared__ float sl[256];
    __shared__ float s_m, s_invl;

    int row = blockIdx.x;
    int tid = threadIdx.x;
    const float* Srow = g_S + (size_t)row * NTOK;

    float m = -INFINITY, l = 0.0f;
    for (int j = tid * 4; j < NTOK; j += 1024) {
        float4 v = *(const float4*)(Srow + j);
        float f[4] = {v.x, v.y, v.z, v.w};
#pragma unroll
        for (int q = 0; q < 4; q++) {
            float nm = fmaxf(m, f[q]);
            l = l * __expf(m - nm) + __expf(f[q] - nm);
            m = nm;
        }
    }
    sm[tid] = m; sl[tid] = l;
    __syncthreads();
    for (int off = 128; off > 0; off >>= 1) {
        if (tid < off) {
            float m2 = sm[tid + off], l2 = sl[tid + off];
            float m1 = sm[tid], l1 = sl[tid];
            float nm = fmaxf(m1, m2);
            sl[tid] = l1 * __expf(m1 - nm) + l2 * __expf(m2 - nm);
            sm[tid] = nm;
        }
        __syncthreads();
    }
    if (tid == 0) { s_m = sm[0]; s_invl = 1.0f / sl[0]; }
    __syncthreads();

    float mm = s_m, invl = s_invl;
    __nv_bfloat16* Ph = g_Ph + (size_t)row * NTOK;
    __nv_bfloat16* Pl = g_Pl + (size_t)row * NTOK;
    for (int j = tid * 4; j < NTOK; j += 1024) {
        float4 v = *(const float4*)(Srow + j);
        float f[4] = {v.x, v.y, v.z, v.w};
        __nv_bfloat16 hh[4], ll[4];
#pragma unroll
        for (int q = 0; q < 4; q++) {
            float p = __expf(f[q] - mm) * invl;
            hh[q] = __float2bfloat16(p);
            ll[q] = __float2bfloat16(p - __bfloat162float(hh[q]));
        }
        ((__nv_bfloat162*)(Ph + j))[0] = __halves2bfloat162(hh[0], hh[1]);
        ((__nv_bfloat162*)(Ph + j))[1] = __halves2bfloat162(hh[2], hh[3]);
        ((__nv_bfloat162*)(Pl + j))[0] = __halves2bfloat162(ll[0], ll[1]);
        ((__nv_bfloat162*)(Pl + j))[1] = __halves2bfloat162(ll[2], ll[3]);
    }
}

// ---------------------------------------------------------------------------
// Output: O = P @ V  (B from transposed V).  grid (64, 8)
// ---------------------------------------------------------------------------
__global__ __launch_bounds__(256, 1) void out_mma(float* __restrict__ O)
{
    extern __shared__ char smem[];
    int tid = threadIdx.x, lane = tid & 31, warp = tid >> 5;
    int wm = warp >> 2, wn = warp & 3;
    int rowBase = blockIdx.x * 128, colBase = blockIdx.y * 128;

    float acc[4][4][4] = {};
    gemm_core<NTOK / KT>(g_Ph, g_Pl, NTOK, g_Vth, g_Vtl, NTOK,
                         rowBase, colBase, smem, acc);

#pragma unroll
    for (int mi = 0; mi < 4; mi++)
#pragma unroll
        for (int ni = 0; ni < 4; ni++) {
            int r = rowBase + wm * 64 + mi * 16 + (lane >> 2);
            int c = colBase + wn * 32 + ni * 8 + (lane & 3) * 2;
            *(float2*)(O + (size_t)r * DIM + c) = make_float2(acc[mi][ni][0], acc[mi][ni][1]);
            *(float2*)(O + (size_t)(r + 8) * DIM + c) = make_float2(acc[mi][ni][2], acc[mi][ni][3]);
        }
}

// ---------------------------------------------------------------------------
extern "C" void kernel_launch(void* const* d_in, const int* in_sizes, int n_in,
                              void* d_out, int out_size)
{
    const float* x  = (const float*)d_in[0];
    const float* ts = (const float*)d_in[1];
    const float* Wq = (const float*)d_in[2];
    const float* bq = (const float*)d_in[3];
    const float* Wk = (const float*)d_in[4];
    const float* bk = (const float*)d_in[5];
    const float* Wv = (const float*)d_in[6];
    const float* bv = (const float*)d_in[7];
    float* out = (float*)d_out;

    cudaFuncSetAttribute(qkv_mma,    cudaFuncAttributeMaxDynamicSharedMemorySize, SMEM_TOTAL);
    cudaFuncSetAttribute(scores_mma, cudaFuncAttributeMaxDynamicSharedMemorySize, SMEM_TOTAL);
    cudaFuncSetAttribute(out_mma,    cudaFuncAttributeMaxDynamicSharedMemorySize, SMEM_TOTAL);

    // resolve device-global addresses for split targets
    __nv_bfloat16 *xh, *xl, *wh0, *wl0;
    cudaGetSymbolAddress((void**)&xh, g_xh);
    cudaGetSymbolAddress((void**)&xl, g_xl);
    cudaGetSymbolAddress((void**)&wh0, g_Wh);
    cudaGetSymbolAddress((void**)&wl0, g_Wl);

    const size_t ND = (size_t)NTOK * DIM, DD = (size_t)DIM * DIM;
    split_kernel<<<(int)(ND / 1024), 256>>>(x, xh, xl, (int)ND);
    split_kernel<<<(int)(DD / 1024), 256>>>(Wq, wh0,          wl0,          (int)DD);
    split_kernel<<<(int)(DD / 1024), 256>>>(Wk, wh0 + DD,     wl0 + DD,     (int)DD);
    split_kernel<<<(int)(DD / 1024), 256>>>(Wv, wh0 + 2 * DD, wl0 + 2 * DD, (int)DD);

    qkv_mma<<<dim3(NTOK / 128, DIM / 128, 3), 256, SMEM_TOTAL>>>(bq, bk, bv);
    scores_mma<<<dim3(NTOK / 128, NTOK / 128), 256, SMEM_TOTAL>>>(ts);
    softmax_kernel<<<NTOK, 256>>>();
    out_mma<<<dim3(NTOK / 128, DIM / 128), 256, SMEM_TOTAL>>>(out);
}

// round 5
// speedup vs baseline: 3.0049x; 1.0042x over previous
#include <cuda_runtime.h>
#include <cuda_bf16.h>
#include <math.h>

#define NTOK 8192
#define DIM  1024
#define KT   32          // k-tile depth (bf16 elements)
#define BPADE 40         // smem row stride in elements (80B = 5*16B)
#define ARR_BYTES 10240  // 128 * 40 * 2
#define STAGE_BYTES 40960
#define NSTAGE 3
#define SMEM_TOTAL (NSTAGE * STAGE_BYTES)

// ---------------------------------------------------------------------------
// Scratch (static device globals)
// ---------------------------------------------------------------------------
__device__ __nv_bfloat16 g_xh[(size_t)NTOK * DIM], g_xl[(size_t)NTOK * DIM];
__device__ __nv_bfloat16 g_Wh[3][(size_t)DIM * DIM], g_Wl[3][(size_t)DIM * DIM];
__device__ __nv_bfloat16 g_Qh[(size_t)NTOK * DIM], g_Ql[(size_t)NTOK * DIM];
__device__ __nv_bfloat16 g_Kh[(size_t)NTOK * DIM], g_Kl[(size_t)NTOK * DIM];
__device__ __nv_bfloat16 g_Vth[(size_t)DIM * NTOK], g_Vtl[(size_t)DIM * NTOK];  // [dim][token]
__device__ __nv_bfloat16 g_Ph[(size_t)NTOK * NTOK], g_Pl[(size_t)NTOK * NTOK];
__device__ float g_S[(size_t)NTOK * NTOK];

// ---------------------------------------------------------------------------
// helpers
// ---------------------------------------------------------------------------
__device__ __forceinline__ unsigned smem_u32(const void* p) {
    return (unsigned)__cvta_generic_to_shared(p);
}
__device__ __forceinline__ void cpa16(unsigned s, const void* g) {
    asm volatile("cp.async.cg.shared.global [%0],[%1],16;" :: "r"(s), "l"(g));
}
__device__ __forceinline__ void cpa_commit() {
    asm volatile("cp.async.commit_group;" ::: "memory");
}
__device__ __forceinline__ void cpa_wait0() {
    asm volatile("cp.async.wait_group 0;" ::: "memory");
}
__device__ __forceinline__ void cpa_wait1() {
    asm volatile("cp.async.wait_group 1;" ::: "memory");
}
__device__ __forceinline__ void ldsm4(unsigned r[4], unsigned addr) {
    asm volatile("ldmatrix.sync.aligned.m8n8.x4.shared.b16 {%0,%1,%2,%3},[%4];"
                 : "=r"(r[0]), "=r"(r[1]), "=r"(r[2]), "=r"(r[3]) : "r"(addr));
}
__device__ __forceinline__ void mma_bf16(float c[4], const unsigned a[4], const unsigned b[2]) {
    asm volatile("mma.sync.aligned.m16n8k16.row.col.f32.bf16.bf16.f32 "
                 "{%0,%1,%2,%3},{%4,%5,%6,%7},{%8,%9},{%0,%1,%2,%3};"
                 : "+f"(c[0]), "+f"(c[1]), "+f"(c[2]), "+f"(c[3])
                 : "r"(a[0]), "r"(a[1]), "r"(a[2]), "r"(a[3]), "r"(b[0]), "r"(b[1]));
}

// ---------------------------------------------------------------------------
// fragment loads for one k16 slice
// ---------------------------------------------------------------------------
__device__ __forceinline__ void load_frags(
    const char* sb, int kk, int lane, int wm, int wn,
    unsigned ah[4][4], unsigned al[4][4], unsigned bh[2][4], unsigned bl[2][4])
{
    const __nv_bfloat16 (*Ah)[BPADE] = (const __nv_bfloat16(*)[BPADE])(sb);
    const __nv_bfloat16 (*Al)[BPADE] = (const __nv_bfloat16(*)[BPADE])(sb + ARR_BYTES);
    const __nv_bfloat16 (*Bh)[BPADE] = (const __nv_bfloat16(*)[BPADE])(sb + 2 * ARR_BYTES);
    const __nv_bfloat16 (*Bl)[BPADE] = (const __nv_bfloat16(*)[BPADE])(sb + 3 * ARR_BYTES);

    int arow = (lane & 7) + ((lane >> 3) & 1) * 8;
    int acol = kk + (lane >> 4) * 8;
#pragma unroll
    for (int mi = 0; mi < 4; mi++) {
        int r = wm * 64 + mi * 16 + arow;
        ldsm4(ah[mi], smem_u32(&Ah[r][acol]));
        ldsm4(al[mi], smem_u32(&Al[r][acol]));
    }
    int brow = (lane & 7) + ((lane >> 4) & 1) * 8;
    int bcol = kk + ((lane >> 3) & 1) * 8;
#pragma unroll
    for (int p = 0; p < 2; p++) {
        int n = wn * 32 + p * 16 + brow;
        ldsm4(bh[p], smem_u32(&Bh[n][bcol]));
        ldsm4(bl[p], smem_u32(&Bl[n][bcol]));
    }
}

// one 128x128xKT tile of split-MMA; all fragment loads issued before MMA stream
__device__ __forceinline__ void mma_tile(const char* sb, int lane, int wm, int wn,
                                         float acc[4][4][4])
{
    unsigned ah[2][4][4], al[2][4][4], bh[2][2][4], bl[2][2][4];
    load_frags(sb, 0,  lane, wm, wn, ah[0], al[0], bh[0], bl[0]);
    load_frags(sb, 16, lane, wm, wn, ah[1], al[1], bh[1], bl[1]);
#pragma unroll
    for (int h = 0; h < 2; h++) {
#pragma unroll
        for (int mi = 0; mi < 4; mi++)
#pragma unroll
            for (int ni = 0; ni < 4; ni++) {
                const unsigned* bhp = &bh[h][ni >> 1][(ni & 1) * 2];
                const unsigned* blp = &bl[h][ni >> 1][(ni & 1) * 2];
                mma_bf16(acc[mi][ni], ah[h][mi], bhp);
                mma_bf16(acc[mi][ni], ah[h][mi], blp);
                mma_bf16(acc[mi][ni], al[h][mi], bhp);
            }
    }
}

// ---------------------------------------------------------------------------
// stage loader: 8 cp.async x 16B per thread into one pipeline slot
// ---------------------------------------------------------------------------
__device__ __forceinline__ void load_stage(
    unsigned st,
    const __nv_bfloat16* gAh0, const __nv_bfloat16* gAh1,
    const __nv_bfloat16* gAl0, const __nv_bfloat16* gAl1,
    const __nv_bfloat16* gBh0, const __nv_bfloat16* gBh1,
    const __nv_bfloat16* gBl0, const __nv_bfloat16* gBl1, int koff)
{
    const unsigned R64 = 64 * BPADE * 2;
    cpa16(st, gAh0 + koff);                      cpa16(st + R64, gAh1 + koff);
    cpa16(st + ARR_BYTES, gAl0 + koff);          cpa16(st + ARR_BYTES + R64, gAl1 + koff);
    cpa16(st + 2 * ARR_BYTES, gBh0 + koff);      cpa16(st + 2 * ARR_BYTES + R64, gBh1 + koff);
    cpa16(st + 3 * ARR_BYTES, gBl0 + koff);      cpa16(st + 3 * ARR_BYTES + R64, gBl1 + koff);
}

// 3-stage pipelined mainloop. A rows at rowBase, B rows at colBase, k-contig.
template <int KITERS>
__device__ __forceinline__ void gemm_core(
    const __nv_bfloat16* __restrict__ Agh, const __nv_bfloat16* __restrict__ Agl, int sA,
    const __nv_bfloat16* __restrict__ Bgh, const __nv_bfloat16* __restrict__ Bgl, int sB,
    int rowBase, int colBase, char* smem, float acc[4][4][4])
{
    int tid = threadIdx.x;
    int row = tid >> 2, ck = (tid & 3) * 8;

    const __nv_bfloat16* gAh0 = Agh + (size_t)(rowBase + row) * sA + ck;
    const __nv_bfloat16* gAh1 = gAh0 + (size_t)64 * sA;
    const __nv_bfloat16* gAl0 = Agl + (size_t)(rowBase + row) * sA + ck;
    const __nv_bfloat16* gAl1 = gAl0 + (size_t)64 * sA;
    const __nv_bfloat16* gBh0 = Bgh + (size_t)(colBase + row) * sB + ck;
    const __nv_bfloat16* gBh1 = gBh0 + (size_t)64 * sB;
    const __nv_bfloat16* gBl0 = Bgl + (size_t)(colBase + row) * sB + ck;
    const __nv_bfloat16* gBl1 = gBl0 + (size_t)64 * sB;

    unsigned s0 = smem_u32(smem) + (row * BPADE + ck) * 2;
    int lane = tid & 31, warp = tid >> 5, wm = warp >> 2, wn = warp & 3;

    // prologue: stages 0 and 1
    load_stage(s0, gAh0, gAh1, gAl0, gAl1, gBh0, gBh1, gBl0, gBl1, 0);
    cpa_commit();
    load_stage(s0 + STAGE_BYTES, gAh0, gAh1, gAl0, gAl1, gBh0, gBh1, gBl0, gBl1, KT);
    cpa_commit();

    for (int it = 0; it < KITERS; it++) {
        if (it == KITERS - 1) cpa_wait0(); else cpa_wait1();
        __syncthreads();
        if (it + 2 < KITERS) {
            load_stage(s0 + ((it + 2) % NSTAGE) * STAGE_BYTES,
                       gAh0, gAh1, gAl0, gAl1, gBh0, gBh1, gBl0, gBl1, (it + 2) * KT);
            cpa_commit();
        }
        mma_tile(smem + (it % NSTAGE) * STAGE_BYTES, lane, wm, wn, acc);
    }
}

// ---------------------------------------------------------------------------
// elementwise fp32 -> bf16 hi/lo split
// ---------------------------------------------------------------------------
__global__ __launch_bounds__(256) void split_kernel(
    const float* __restrict__ src, __nv_bfloat16* __restrict__ h,
    __nv_bfloat16* __restrict__ l, int n)
{
    int i = (blockIdx.x * 256 + threadIdx.x) * 4;
    if (i >= n) return;
    float4 v = *(const float4*)(src + i);
    float f[4] = {v.x, v.y, v.z, v.w};
    __nv_bfloat16 hh[4], ll[4];
#pragma unroll
    for (int j = 0; j < 4; j++) {
        hh[j] = __float2bfloat16(f[j]);
        ll[j] = __float2bfloat16(f[j] - __bfloat162float(hh[j]));
    }
    ((__nv_bfloat162*)(h + i))[0] = __halves2bfloat162(hh[0], hh[1]);
    ((__nv_bfloat162*)(h + i))[1] = __halves2bfloat162(hh[2], hh[3]);
    ((__nv_bfloat162*)(l + i))[0] = __halves2bfloat162(ll[0], ll[1]);
    ((__nv_bfloat162*)(l + i))[1] = __halves2bfloat162(ll[2], ll[3]);
}

// ---------------------------------------------------------------------------
// QKV: out = x @ W^T + b, split-stored. z=2 (V) stored transposed [dim][token].
// grid (64, 8, 3), block 256
// ---------------------------------------------------------------------------
__global__ __launch_bounds__(256, 1) void qkv_mma(
    const float* __restrict__ bq, const float* __restrict__ bk,
    const float* __restrict__ bv)
{
    extern __shared__ char smem[];
    int z = blockIdx.z;
    const float* bias = (z == 0) ? bq : (z == 1) ? bk : bv;

    int tid = threadIdx.x, lane = tid & 31, warp = tid >> 5;
    int wm = warp >> 2, wn = warp & 3;
    int rowBase = blockIdx.x * 128, colBase = blockIdx.y * 128;

    float acc[4][4][4] = {};
    gemm_core<DIM / KT>(g_xh, g_xl, DIM, g_Wh[z], g_Wl[z], DIM,
                        rowBase, colBase, smem, acc);

    if (z < 2) {
        __nv_bfloat16* oh = (z == 0) ? g_Qh : g_Kh;
        __nv_bfloat16* ol = (z == 0) ? g_Ql : g_Kl;
#pragma unroll
        for (int mi = 0; mi < 4; mi++)
#pragma unroll
            for (int ni = 0; ni < 4; ni++) {
                int r = rowBase + wm * 64 + mi * 16 + (lane >> 2);
                int c = colBase + wn * 32 + ni * 8 + (lane & 3) * 2;
                float b0 = bias[c], b1 = bias[c + 1];
#pragma unroll
                for (int hr = 0; hr < 2; hr++) {
                    float v0 = acc[mi][ni][hr * 2] + b0;
                    float v1 = acc[mi][ni][hr * 2 + 1] + b1;
                    __nv_bfloat16 h0 = __float2bfloat16(v0), h1 = __float2bfloat16(v1);
                    size_t o = (size_t)(r + hr * 8) * DIM + c;
                    *(__nv_bfloat162*)(oh + o) = __halves2bfloat162(h0, h1);
                    *(__nv_bfloat162*)(ol + o) = __halves2bfloat162(
                        __float2bfloat16(v0 - __bfloat162float(h0)),
                        __float2bfloat16(v1 - __bfloat162float(h1)));
                }
            }
    } else {
        // V: transpose via smem, store [dim][token]
        __syncthreads();  // done with mainloop buffers
        __nv_bfloat16 (*Th)[136] = (__nv_bfloat16(*)[136])(smem);
        __nv_bfloat16 (*Tl)[136] = (__nv_bfloat16(*)[136])(smem + 128 * 136 * 2);
#pragma unroll
        for (int mi = 0; mi < 4; mi++)
#pragma unroll
            for (int ni = 0; ni < 4; ni++) {
                int rL = wm * 64 + mi * 16 + (lane >> 2);
                int cL = wn * 32 + ni * 8 + (lane & 3) * 2;
                float b0 = bias[colBase + cL], b1 = bias[colBase + cL + 1];
#pragma unroll
                for (int hr = 0; hr < 2; hr++) {
                    float v0 = acc[mi][ni][hr * 2] + b0;
                    float v1 = acc[mi][ni][hr * 2 + 1] + b1;
                    __nv_bfloat16 h0 = __float2bfloat16(v0), h1 = __float2bfloat16(v1);
                    Th[cL][rL + hr * 8] = h0;
                    Th[cL + 1][rL + hr * 8] = h1;
                    Tl[cL][rL + hr * 8] = __float2bfloat16(v0 - __bfloat162float(h0));
                    Tl[cL + 1][rL + hr * 8] = __float2bfloat16(v1 - __bfloat162float(h1));
                }
            }
        __syncthreads();
#pragma unroll
        for (int j = 0; j < 8; j++) {
            int idx = j * 256 + tid;
            int cRow = idx >> 4, ch = (idx & 15) * 8;
            float4 vh = *(float4*)&Th[cRow][ch];
            float4 vl = *(float4*)&Tl[cRow][ch];
            size_t o = (size_t)(colBase + cRow) * NTOK + rowBase + ch;
            *(float4*)(g_Vth + o) = vh;
            *(float4*)(g_Vtl + o) = vl;
        }
    }
}

// ---------------------------------------------------------------------------
// Scores: S = (Q @ K^T)/32 - |dt|/86400   (log(exp+eps) ~ -d to 2.2e-6)
// grid (64, 64), block 256
// ---------------------------------------------------------------------------
__global__ __launch_bounds__(256, 1) void scores_mma(const float* __restrict__ ts)
{
    extern __shared__ char smem[];
    int tid = threadIdx.x, lane = tid & 31, warp = tid >> 5;
    int wm = warp >> 2, wn = warp & 3;
    int rowBase = blockIdx.x * 128, colBase = blockIdx.y * 128;

    float acc[4][4][4] = {};
    gemm_core<DIM / KT>(g_Qh, g_Ql, DIM, g_Kh, g_Kl, DIM,
                        rowBase, colBase, smem, acc);

    const float inv_scale = 1.0f / 32.0f;
    const float inv_T = 1.0f / 86400.0f;

#pragma unroll
    for (int mi = 0; mi < 4; mi++) {
        int r = rowBase + wm * 64 + mi * 16 + (lane >> 2);
        float t_r0 = ts[r], t_r1 = ts[r + 8];
#pragma unroll
        for (int ni = 0; ni < 4; ni++) {
            int c = colBase + wn * 32 + ni * 8 + (lane & 3) * 2;
            float tc0 = ts[c], tc1 = ts[c + 1];
            float b00 = -fabsf(t_r0 - tc0) * inv_T;
            float b01 = -fabsf(t_r0 - tc1) * inv_T;
            float b10 = -fabsf(t_r1 - tc0) * inv_T;
            float b11 = -fabsf(t_r1 - tc1) * inv_T;
            *(float2*)(g_S + (size_t)r * NTOK + c) =
                make_float2(acc[mi][ni][0] * inv_scale + b00, acc[mi][ni][1] * inv_scale + b01);
            *(float2*)(g_S + (size_t)(r + 8) * NTOK + c) =
                make_float2(acc[mi][ni][2] * inv_scale + b10, acc[mi][ni][3] * inv_scale + b11);
        }
    }
}

// ---------------------------------------------------------------------------
// Row softmax: S -> P (bf16 hi/lo).  grid NTOK, block 256
// ---------------------------------------------------------------------------
__global__ __launch_bounds__(256) void softmax_kernel()
{
    __shared__ float sm[256];
    __shared__ float sl[256];
    __shared__ float s_m, s_invl;

    int row = blockIdx.x;
    int tid = threadIdx.x;
    const float* Srow = g_S + (size_t)row * NTOK;

    float m = -INFINITY, l = 0.0f;
    for (int j = tid * 4; j < NTOK; j += 1024) {
        float4 v = *(const float4*)(Srow + j);
        float f[4] = {v.x, v.y, v.z, v.w};
#pragma unroll
        for (int q = 0; q < 4; q++) {
            float nm = fmaxf(m, f[q]);
            l = l * __expf(m - nm) + __expf(f[q] - nm);
            m = nm;
        }
    }
    sm[tid] = m; sl[tid] = l;
    __syncthreads();
    for (int off = 128; off > 0; off >>= 1) {
        if (tid < off) {
            float m2 = sm[tid + off], l2 = sl[tid + off];
            float m1 = sm[tid], l1 = sl[tid];
            float nm = fmaxf(m1, m2);
            sl[tid] = l1 * __expf(m1 - nm) + l2 * __expf(m2 - nm);
            sm[tid] = nm;
        }
        __syncthreads();
    }
    if (tid == 0) { s_m = sm[0]; s_invl = 1.0f / sl[0]; }
    __syncthreads();

    float mm = s_m, invl = s_invl;
    __nv_bfloat16* Ph = g_Ph + (size_t)row * NTOK;
    __nv_bfloat16* Pl = g_Pl + (size_t)row * NTOK;
    for (int j = tid * 4; j < NTOK; j += 1024) {
        float4 v = *(const float4*)(Srow + j);
        float f[4] = {v.x, v.y, v.z, v.w};
        __nv_bfloat16 hh[4], ll[4];
#pragma unroll
        for (int q = 0; q < 4; q++) {
            float p = __expf(f[q] - mm) * invl;
            hh[q] = __float2bfloat16(p);
            ll[q] = __float2bfloat16(p - __bfloat162float(hh[q]));
        }
        ((__nv_bfloat162*)(Ph + j))[0] = __halves2bfloat162(hh[0], hh[1]);
        ((__nv_bfloat162*)(Ph + j))[1] = __halves2bfloat162(hh[2], hh[3]);
        ((__nv_bfloat162*)(Pl + j))[0] = __halves2bfloat162(ll[0], ll[1]);
        ((__nv_bfloat162*)(Pl + j))[1] = __halves2bfloat162(ll[2], ll[3]);
    }
}

// ---------------------------------------------------------------------------
// Output: O = P @ V  (B from transposed V).  grid (64, 8)
// ---------------------------------------------------------------------------
__global__ __launch_bounds__(256, 1) void out_mma(float* __restrict__ O)
{
    extern __shared__ char smem[];
    int tid = threadIdx.x, lane = tid & 31, warp = tid >> 5;
    int wm = warp >> 2, wn = warp & 3;
    int rowBase = blockIdx.x * 128, colBase = blockIdx.y * 128;

    float acc[4][4][4] = {};
    gemm_core<NTOK / KT>(g_Ph, g_Pl, NTOK, g_Vth, g_Vtl, NTOK,
                         rowBase, colBase, smem, acc);

#pragma unroll
    for (int mi = 0; mi < 4; mi++)
#pragma unroll
        for (int ni = 0; ni < 4; ni++) {
            int r = rowBase + wm * 64 + mi * 16 + (lane >> 2);
            int c = colBase + wn * 32 + ni * 8 + (lane & 3) * 2;
            *(float2*)(O + (size_t)r * DIM + c) = make_float2(acc[mi][ni][0], acc[mi][ni][1]);
            *(float2*)(O + (size_t)(r + 8) * DIM + c) = make_float2(acc[mi][ni][2], acc[mi][ni][3]);
        }
}

// ---------------------------------------------------------------------------
extern "C" void kernel_launch(void* const* d_in, const int* in_sizes, int n_in,
                              void* d_out, int out_size)
{
    const float* x  = (const float*)d_in[0];
    const float* ts = (const float*)d_in[1];
    const float* Wq = (const float*)d_in[2];
    const float* bq = (const float*)d_in[3];
    const float* Wk = (const float*)d_in[4];
    const float* bk = (const float*)d_in[5];
    const float* Wv = (const float*)d_in[6];
    const float* bv = (const float*)d_in[7];
    float* out = (float*)d_out;

    cudaFuncSetAttribute(qkv_mma,    cudaFuncAttributeMaxDynamicSharedMemorySize, SMEM_TOTAL);
    cudaFuncSetAttribute(scores_mma, cudaFuncAttributeMaxDynamicSharedMemorySize, SMEM_TOTAL);
    cudaFuncSetAttribute(out_mma,    cudaFuncAttributeMaxDynamicSharedMemorySize, SMEM_TOTAL);

    __nv_bfloat16 *xh, *xl, *wh0, *wl0;
    cudaGetSymbolAddress((void**)&xh, g_xh);
    cudaGetSymbolAddress((void**)&xl, g_xl);
    cudaGetSymbolAddress((void**)&wh0, g_Wh);
    cudaGetSymbolAddress((void**)&wl0, g_Wl);

    const size_t ND = (size_t)NTOK * DIM, DD = (size_t)DIM * DIM;
    split_kernel<<<(int)(ND / 1024), 256>>>(x, xh, xl, (int)ND);
    split_kernel<<<(int)(DD / 1024), 256>>>(Wq, wh0,          wl0,          (int)DD);
    split_kernel<<<(int)(DD / 1024), 256>>>(Wk, wh0 + DD,     wl0 + DD,     (int)DD);
    split_kernel<<<(int)(DD / 1024), 256>>>(Wv, wh0 + 2 * DD, wl0 + 2 * DD, (int)DD);

    qkv_mma<<<dim3(NTOK / 128, DIM / 128, 3), 256, SMEM_TOTAL>>>(bq, bk, bv);
    scores_mma<<<dim3(NTOK / 128, NTOK / 128), 256, SMEM_TOTAL>>>(ts);
    softmax_kernel<<<NTOK, 256>>>();
    out_mma<<<dim3(NTOK / 128, DIM / 128), 256, SMEM_TOTAL>>>(out);
}